// round 1
// baseline (speedup 1.0000x reference)
#include <cuda_runtime.h>
#include <math.h>

#define NN 512
#define DD 512
#define LN_EPS 1e-5f

// Scratch: left rows [0, N*D), right rows [N*D, 2*N*D). 2 MB, L2-resident.
__device__ float g_LR[2 * NN * DD];

// ---------------------------------------------------------------------------
// GEMM: left = E @ W1[:D],  right = E @ W1[D:] + b1   (z = 0 / 1)
// BM=BN=64, BK=16, 256 threads, 4x4 micro-tile per thread.
// ---------------------------------------------------------------------------
#define BM 64
#define BN 64
#define BK 16

__global__ __launch_bounds__(256) void gemm_kernel(
    const float* __restrict__ E, const float* __restrict__ W1,
    const float* __restrict__ b1)
{
    __shared__ float As[BK][BM + 4];   // As[k][m], row stride 68 floats (272B, 16B-aligned)
    __shared__ float Bs[BK][BN + 4];

    const int z = blockIdx.z;
    const float* W = W1 + z * DD * DD;
    float* out = g_LR + z * NN * DD;

    const int m0 = blockIdx.y * BM;
    const int n0 = blockIdx.x * BN;
    const int t = threadIdx.x;

    const int am = t >> 2, ak = (t & 3) << 2;   // A tile: 64 rows x 16 k (1 float4/thread)
    const int bk = t >> 4, bn = (t & 15) << 2;  // B tile: 16 k x 64 cols (1 float4/thread)
    const int ty = t >> 4, tx = t & 15;

    float acc[4][4];
#pragma unroll
    for (int i = 0; i < 4; i++)
#pragma unroll
        for (int j = 0; j < 4; j++) acc[i][j] = 0.f;

    for (int k0 = 0; k0 < DD; k0 += BK) {
        float4 av = *(const float4*)&E[(m0 + am) * DD + k0 + ak];
        As[ak + 0][am] = av.x;
        As[ak + 1][am] = av.y;
        As[ak + 2][am] = av.z;
        As[ak + 3][am] = av.w;
        *(float4*)&Bs[bk][bn] = *(const float4*)&W[(k0 + bk) * DD + n0 + bn];
        __syncthreads();
#pragma unroll
        for (int k = 0; k < BK; k++) {
            float4 a = *(const float4*)&As[k][ty << 2];
            float4 b = *(const float4*)&Bs[k][tx << 2];
            acc[0][0] = fmaf(a.x, b.x, acc[0][0]);
            acc[0][1] = fmaf(a.x, b.y, acc[0][1]);
            acc[0][2] = fmaf(a.x, b.z, acc[0][2]);
            acc[0][3] = fmaf(a.x, b.w, acc[0][3]);
            acc[1][0] = fmaf(a.y, b.x, acc[1][0]);
            acc[1][1] = fmaf(a.y, b.y, acc[1][1]);
            acc[1][2] = fmaf(a.y, b.z, acc[1][2]);
            acc[1][3] = fmaf(a.y, b.w, acc[1][3]);
            acc[2][0] = fmaf(a.z, b.x, acc[2][0]);
            acc[2][1] = fmaf(a.z, b.y, acc[2][1]);
            acc[2][2] = fmaf(a.z, b.z, acc[2][2]);
            acc[2][3] = fmaf(a.z, b.w, acc[2][3]);
            acc[3][0] = fmaf(a.w, b.x, acc[3][0]);
            acc[3][1] = fmaf(a.w, b.y, acc[3][1]);
            acc[3][2] = fmaf(a.w, b.z, acc[3][2]);
            acc[3][3] = fmaf(a.w, b.w, acc[3][3]);
        }
        __syncthreads();
    }

#pragma unroll
    for (int i = 0; i < 4; i++) {
        int row = m0 + (ty << 2) + i;
#pragma unroll
        for (int j = 0; j < 4; j++) {
            int col = n0 + (tx << 2) + j;
            float bias = z ? b1[col] : 0.f;
            out[row * DD + col] = acc[i][j] + bias;
        }
    }
}

// ---------------------------------------------------------------------------
// Pairwise kernel: one warp per pair, 8x8 pair tile per block (upper triangle).
// Two passes with h in registers; GELU via MUFU tanh.approx.
// ---------------------------------------------------------------------------
#define TI 8
#define TT (NN / TI)   // 64 tiles per side; blocks = TT*(TT+1)/2 = 2080

__global__ __launch_bounds__(256) void pair_kernel(
    const float* __restrict__ gamma, const float* __restrict__ beta,
    const float* __restrict__ W2, const float* __restrict__ b2,
    float* __restrict__ out)
{
    __shared__ float sl[TI][DD];
    __shared__ float sr[TI][DD];

    // Decode linear block id -> upper-triangular tile (ti <= tj).
    // off(t) = t*TT - t*(t-1)/2
    int bid = blockIdx.x;
    int ti = (int)((2.0f * TT + 1.0f -
                    sqrtf((2.0f * TT + 1.0f) * (2.0f * TT + 1.0f) - 8.0f * (float)bid)) * 0.5f);
    if (ti < 0) ti = 0;
    if (ti > TT - 1) ti = TT - 1;
    while (ti > 0 && (ti * TT - ((ti * (ti - 1)) >> 1)) > bid) ti--;
    while (((ti + 1) * TT - (((ti + 1) * ti) >> 1)) <= bid) ti++;
    const int tj = ti + bid - (ti * TT - ((ti * (ti - 1)) >> 1));

    const int t = threadIdx.x;
    const int lane = t & 31;
    const int w = t >> 5;

    const float* L = g_LR;
    const float* R = g_LR + NN * DD;

    // Stage 8 left + 8 right rows into smem (float4, coalesced).
#pragma unroll
    for (int c = 0; c < 4; c++) {
        int idx = c * 256 + t;          // float4 index 0..1023
        int r = idx >> 7;               // 128 float4 per row
        int col = (idx & 127) << 2;
        *(float4*)&sl[r][col] = *(const float4*)&L[(ti * TI + r) * DD + col];
        *(float4*)&sr[r][col] = *(const float4*)&R[(tj * TI + r) * DD + col];
    }

    // Per-lane parameter registers (d = lane + 32k), identical across warps -> L1 hits.
    float gR[16], bR[16], wR[16];
#pragma unroll
    for (int k = 0; k < 16; k++) {
        int d = lane + (k << 5);
        gR[k] = gamma[d];
        bR[k] = beta[d];
        wR[k] = W2[d];
    }
    const float b2v = b2[0];

    __syncthreads();

    const int i = ti * TI + w;
    float lrow[16];
#pragma unroll
    for (int k = 0; k < 16; k++) lrow[k] = sl[w][lane + (k << 5)];

    for (int jj = 0; jj < TI; jj++) {
        int j = tj * TI + jj;
        if (i > j) continue;            // only diagonal tiles hit this; warp-uniform

        // Pass 1: h = l + r, accumulate sum / sumsq
        float h[16];
        float s = 0.f, q = 0.f;
#pragma unroll
        for (int k = 0; k < 16; k++) {
            float v = lrow[k] + sr[jj][lane + (k << 5)];
            h[k] = v;
            s += v;
            q = fmaf(v, v, q);
        }
#pragma unroll
        for (int o = 16; o > 0; o >>= 1) {
            s += __shfl_xor_sync(0xffffffffu, s, o);
            q += __shfl_xor_sync(0xffffffffu, q, o);
        }
        const float mu = s * (1.0f / DD);
        const float var = fmaf(-mu, mu, q * (1.0f / DD));
        const float rstd = rsqrtf(var + LN_EPS);
        const float cc = -mu * rstd;

        // Pass 2: affine + GELU(tanh) + dot(W2)
        float acc = 0.f;
#pragma unroll
        for (int k = 0; k < 16; k++) {
            float x = fmaf(h[k], rstd, cc);
            x = fmaf(x, gR[k], bR[k]);
            float x2 = x * x;
            float u = x * fmaf(0.0356774081f, x2, 0.7978845608f);
            float th;
            asm("tanh.approx.f32 %0, %1;" : "=f"(th) : "f"(u));
            float xh = 0.5f * x;
            float g = fmaf(xh, th, xh);
            acc = fmaf(g, wR[k], acc);
        }
#pragma unroll
        for (int o = 16; o > 0; o >>= 1)
            acc += __shfl_xor_sync(0xffffffffu, acc, o);

        if (lane == 0) {
            float zv = acc + b2v;
            float sig = 1.0f / (1.0f + __expf(-zv));
            out[i * NN + j] = sig;
            out[j * NN + i] = sig;
        }
    }
}

// ---------------------------------------------------------------------------
extern "C" void kernel_launch(void* const* d_in, const int* in_sizes, int n_in,
                              void* d_out, int out_size)
{
    const float* E     = (const float*)d_in[0];  // [N, D]
    const float* W1    = (const float*)d_in[1];  // [2D, D]
    const float* b1    = (const float*)d_in[2];  // [D]
    const float* gamma = (const float*)d_in[3];  // [D]
    const float* beta  = (const float*)d_in[4];  // [D]
    const float* W2    = (const float*)d_in[5];  // [D, 1]
    const float* b2    = (const float*)d_in[6];  // [1]
    float* out = (float*)d_out;                  // [N, N]

    dim3 ggrid(NN / BN, NN / BM, 2);
    gemm_kernel<<<ggrid, 256>>>(E, W1, b1);

    const int nblocks = TT * (TT + 1) / 2;       // 2080
    pair_kernel<<<nblocks, 256>>>(gamma, beta, W2, b2, out);
}

// round 2
// speedup vs baseline: 1.0950x; 1.0950x over previous
#include <cuda_runtime.h>
#include <math.h>

#define NN 512
#define DD 512
#define LN_EPS 1e-5f

typedef unsigned long long ull;

// ---------------- f32x2 packed helpers (sm_103a FFMA2 path) ----------------
__device__ __forceinline__ ull pk(float lo, float hi) {
    ull r; asm("mov.b64 %0, {%1, %2};" : "=l"(r) : "f"(lo), "f"(hi)); return r;
}
__device__ __forceinline__ ull pkdup(float v) {
    ull r; asm("mov.b64 %0, {%1, %1};" : "=l"(r) : "f"(v)); return r;
}
__device__ __forceinline__ void upk(ull v, float& lo, float& hi) {
    asm("mov.b64 {%0, %1}, %2;" : "=f"(lo), "=f"(hi) : "l"(v));
}
__device__ __forceinline__ ull fma2(ull a, ull b, ull c) {
    ull r; asm("fma.rn.f32x2 %0, %1, %2, %3;" : "=l"(r) : "l"(a), "l"(b), "l"(c)); return r;
}
__device__ __forceinline__ ull add2(ull a, ull b) {
    ull r; asm("add.rn.f32x2 %0, %1, %2;" : "=l"(r) : "l"(a), "l"(b)); return r;
}
__device__ __forceinline__ ull mul2(ull a, ull b) {
    ull r; asm("mul.rn.f32x2 %0, %1, %2;" : "=l"(r) : "l"(a), "l"(b)); return r;
}
__device__ __forceinline__ float tanh_approx(float x) {
    float r; asm("tanh.approx.f32 %0, %1;" : "=f"(r) : "f"(x)); return r;
}

// Scratch: left rows [0, N*D), right rows [N*D, 2*N*D). 2 MB, L2-resident.
__device__ float g_LR[2 * NN * DD];

// ---------------------------------------------------------------------------
// GEMM: left = E @ W1[:D],  right = E @ W1[D:] + b1   (z = 0 / 1)
// BM=BN=64, BK=16, 256 threads, 4x4 micro-tile, packed FFMA2 inner loop.
// ---------------------------------------------------------------------------
#define BM 64
#define BN 64
#define BK 16

__global__ __launch_bounds__(256) void gemm_kernel(
    const float* __restrict__ E, const float* __restrict__ W1,
    const float* __restrict__ b1)
{
    __shared__ float As[BK][BM + 4];
    __shared__ float Bs[BK][BN + 4];

    const int z = blockIdx.z;
    const float* W = W1 + z * DD * DD;
    float* out = g_LR + z * NN * DD;

    const int m0 = blockIdx.y * BM;
    const int n0 = blockIdx.x * BN;
    const int t = threadIdx.x;

    const int am = t >> 2, ak = (t & 3) << 2;
    const int bk = t >> 4, bn = (t & 15) << 2;
    const int ty = t >> 4, tx = t & 15;

    ull acc[4][2];
#pragma unroll
    for (int i = 0; i < 4; i++) { acc[i][0] = 0ull; acc[i][1] = 0ull; }

    for (int k0 = 0; k0 < DD; k0 += BK) {
        float4 av = *(const float4*)&E[(m0 + am) * DD + k0 + ak];
        As[ak + 0][am] = av.x;
        As[ak + 1][am] = av.y;
        As[ak + 2][am] = av.z;
        As[ak + 3][am] = av.w;
        *(float4*)&Bs[bk][bn] = *(const float4*)&W[(k0 + bk) * DD + n0 + bn];
        __syncthreads();
#pragma unroll
        for (int k = 0; k < BK; k++) {
            float4 a = *(const float4*)&As[k][ty << 2];
            float4 b = *(const float4*)&Bs[k][tx << 2];
            ull b01 = pk(b.x, b.y);
            ull b23 = pk(b.z, b.w);
            ull a0 = pkdup(a.x), a1 = pkdup(a.y), a2 = pkdup(a.z), a3 = pkdup(a.w);
            acc[0][0] = fma2(a0, b01, acc[0][0]);
            acc[0][1] = fma2(a0, b23, acc[0][1]);
            acc[1][0] = fma2(a1, b01, acc[1][0]);
            acc[1][1] = fma2(a1, b23, acc[1][1]);
            acc[2][0] = fma2(a2, b01, acc[2][0]);
            acc[2][1] = fma2(a2, b23, acc[2][1]);
            acc[3][0] = fma2(a3, b01, acc[3][0]);
            acc[3][1] = fma2(a3, b23, acc[3][1]);
        }
        __syncthreads();
    }

#pragma unroll
    for (int i = 0; i < 4; i++) {
        int row = m0 + (ty << 2) + i;
        int col = n0 + (tx << 2);
        float4 r;
        upk(acc[i][0], r.x, r.y);
        upk(acc[i][1], r.z, r.w);
        if (z) {
            r.x += b1[col + 0];
            r.y += b1[col + 1];
            r.z += b1[col + 2];
            r.w += b1[col + 3];
        }
        *(float4*)&out[row * DD + col] = r;
    }
}

// ---------------------------------------------------------------------------
// Pairwise kernel: one warp per pair, 8x8 pair tile per block (upper triangle).
// Packed f32x2 math: lane handles 8 packed pairs, pair k = elems (64k+2L, +1).
// ---------------------------------------------------------------------------
#define TI 8
#define TT (NN / TI)   // 64; blocks = TT*(TT+1)/2 = 2080

__global__ __launch_bounds__(256) void pair_kernel(
    const float* __restrict__ gamma, const float* __restrict__ beta,
    const float* __restrict__ W2, const float* __restrict__ b2,
    float* __restrict__ out)
{
    __shared__ float sl[TI][DD];
    __shared__ float sr[TI][DD];

    // Decode linear block id -> upper-triangular tile (ti <= tj).
    int bid = blockIdx.x;
    int ti = (int)((2.0f * TT + 1.0f -
                    sqrtf((2.0f * TT + 1.0f) * (2.0f * TT + 1.0f) - 8.0f * (float)bid)) * 0.5f);
    if (ti < 0) ti = 0;
    if (ti > TT - 1) ti = TT - 1;
    while (ti > 0 && (ti * TT - ((ti * (ti - 1)) >> 1)) > bid) ti--;
    while (((ti + 1) * TT - (((ti + 1) * ti) >> 1)) <= bid) ti++;
    const int tj = ti + bid - (ti * TT - ((ti * (ti - 1)) >> 1));

    const int t = threadIdx.x;
    const int lane = t & 31;
    const int w = t >> 5;

    const float* L = g_LR;
    const float* R = g_LR + NN * DD;

    // Stage 8 left + 8 right rows into smem (float4, coalesced).
#pragma unroll
    for (int c = 0; c < 4; c++) {
        int idx = c * 256 + t;
        int r = idx >> 7;
        int col = (idx & 127) << 2;
        *(float4*)&sl[r][col] = *(const float4*)&L[(ti * TI + r) * DD + col];
        *(float4*)&sr[r][col] = *(const float4*)&R[(tj * TI + r) * DD + col];
    }

    // Packed per-lane parameters: pair k covers d = 64k + 2*lane.
    ull g2[8], be2[8], hw2[8];
#pragma unroll
    for (int k = 0; k < 8; k++) {
        int d = (k << 6) + (lane << 1);
        float2 gv = *(const float2*)&gamma[d];
        float2 bv = *(const float2*)&beta[d];
        float2 wv = *(const float2*)&W2[d];
        g2[k] = pk(gv.x, gv.y);
        be2[k] = pk(bv.x, bv.y);
        hw2[k] = pk(0.5f * wv.x, 0.5f * wv.y);   // fold GELU's 0.5 into W2
    }
    const float b2v = b2[0];
    const ull C1 = pkdup(0.0356774081f);
    const ull C0 = pkdup(0.7978845608f);

    __syncthreads();

    const int i = ti * TI + w;

    // Preload this warp's left row, packed.
    ull lrow[8];
#pragma unroll
    for (int k = 0; k < 8; k++)
        lrow[k] = *(const ull*)&sl[w][(k << 6) + (lane << 1)];

    for (int jj = 0; jj < TI; jj++) {
        int j = tj * TI + jj;
        if (i > j) continue;   // only diagonal tiles hit this; warp-uniform

        // Pass 1: h = l + r, packed sum / sumsq
        ull h2[8];
        ull s2 = 0ull, q2 = 0ull;
#pragma unroll
        for (int k = 0; k < 8; k++) {
            ull r2 = *(const ull*)&sr[jj][(k << 6) + (lane << 1)];
            ull v = add2(lrow[k], r2);
            h2[k] = v;
            s2 = add2(s2, v);
            q2 = fma2(v, v, q2);
        }
        float slo, shi, qlo, qhi;
        upk(s2, slo, shi);
        upk(q2, qlo, qhi);
        float s = slo + shi, q = qlo + qhi;
#pragma unroll
        for (int o = 16; o > 0; o >>= 1) {
            s += __shfl_xor_sync(0xffffffffu, s, o);
            q += __shfl_xor_sync(0xffffffffu, q, o);
        }
        const float mu = s * (1.0f / DD);
        const float var = fmaf(-mu, mu, q * (1.0f / DD));
        const float rstd = rsqrtf(var + LN_EPS);
        const ull rstd2 = pkdup(rstd);
        const ull cc2 = pkdup(-mu * rstd);

        // Pass 2: affine + GELU(tanh) + dot(W2), all packed.
        ull accA = 0ull, accB = 0ull;
#pragma unroll
        for (int k = 0; k < 8; k++) {
            ull x = fma2(h2[k], rstd2, cc2);
            x = fma2(x, g2[k], be2[k]);
            ull x2 = mul2(x, x);
            ull p = fma2(x2, C1, C0);
            ull u = mul2(x, p);
            float ulo, uhi;
            upk(u, ulo, uhi);
            ull th = pk(tanh_approx(ulo), tanh_approx(uhi));
            ull xw = mul2(x, hw2[k]);          // 0.5 * x * w
            accA = fma2(xw, th, accA);          // sum 0.5*x*w*tanh
            accB = add2(accB, xw);              // sum 0.5*x*w
        }
        float alo, ahi, blo, bhi;
        upk(accA, alo, ahi);
        upk(accB, blo, bhi);
        float acc = (alo + ahi) + (blo + bhi);
#pragma unroll
        for (int o = 16; o > 0; o >>= 1)
            acc += __shfl_xor_sync(0xffffffffu, acc, o);

        if (lane == 0) {
            float zv = acc + b2v;
            float e = __expf(-zv);
            float sig = __fdividef(1.0f, 1.0f + e);
            out[i * NN + j] = sig;
            out[j * NN + i] = sig;
        }
    }
}

// ---------------------------------------------------------------------------
extern "C" void kernel_launch(void* const* d_in, const int* in_sizes, int n_in,
                              void* d_out, int out_size)
{
    const float* E     = (const float*)d_in[0];  // [N, D]
    const float* W1    = (const float*)d_in[1];  // [2D, D]
    const float* b1    = (const float*)d_in[2];  // [D]
    const float* gamma = (const float*)d_in[3];  // [D]
    const float* beta  = (const float*)d_in[4];  // [D]
    const float* W2    = (const float*)d_in[5];  // [D, 1]
    const float* b2    = (const float*)d_in[6];  // [1]
    float* out = (float*)d_out;                  // [N, N]

    dim3 ggrid(NN / BN, NN / BM, 2);
    gemm_kernel<<<ggrid, 256>>>(E, W1, b1);

    const int nblocks = TT * (TT + 1) / 2;       // 2080
    pair_kernel<<<nblocks, 256>>>(gamma, beta, W2, b2, out);
}